// round 12
// baseline (speedup 1.0000x reference)
#include <cuda_runtime.h>
#include <cuda_bf16.h>

#define NB   8
#define NL   64
#define NH   8
#define ND   32
#define NHID 256

// ---------------- static scratch (no runtime allocation) ----------------
__device__ __align__(16) float g_WqkvT[NHID * 3 * NHID];   // [c][m*256+o]
__device__ __align__(16) float g_WsT[NHID * 64];           // [c][o2] (sq|sv)
__device__ __align__(16) float g_q [NB * NH * NL * ND];    // [b][h][l][d]
__device__ __align__(16) float g_k [NB * NH * NL * ND];
__device__ __align__(16) float g_v [NB * NH * NL * ND];
__device__ __align__(16) float g_kw[NB * NH * NL * ND];    // Wtk^T k
__device__ float g_bk[NB * NH * NL];                       // btk . k
__device__ __align__(16) float g_sq[NB * NL * NL * ND];    // [b][i][j][d]
__device__ __align__(16) float g_sv[NB * NL * NL * ND];
__device__ __align__(16) float g_qw[NB * NL * NL * NH * ND]; // [b][i][j][h][d] = Wtq^T q5
__device__ float g_bq5[NB * NL * NL * NH];                 // btq . q5
__device__ float g_Zp[NB * NL * NH * NL];                  // [b][i][h][k]
__device__ __align__(16) float g_Cp[NB * NL * NH * NL * ND]; // [b][i][h][k][d]

// ---------------- K0: transpose weights ----------------
__global__ void k_prep(const float* __restrict__ Wq, const float* __restrict__ Wk,
                       const float* __restrict__ Wv, const float* __restrict__ Wsq,
                       const float* __restrict__ Wsv)
{
    int c = blockIdx.x;                  // 0..255
    int t = threadIdx.x;                 // 0..767
    int m = t >> 8, o = t & 255;
    const float* W = (m == 0) ? Wq : (m == 1) ? Wk : Wv;
    g_WqkvT[c * 768 + t] = W[o * NHID + c];
    if (t < 64)
        g_WsT[c * 64 + t] = (t < 32) ? Wsq[t * NHID + c] : Wsv[(t - 32) * NHID + c];
}

// ---------------- K1: q,k,v projections (4 rows / block) ----------------
__global__ __launch_bounds__(256)
void k_qkv(const float* __restrict__ hs, const float* __restrict__ bq,
           const float* __restrict__ bk, const float* __restrict__ bv)
{
    __shared__ __align__(16) float rows[4 * NHID];
    int r0 = blockIdx.x * 4;             // 128 blocks * 4 = 512 rows (b*64+l)
    int t = threadIdx.x;                 // output channel o
    float4* r4 = reinterpret_cast<float4*>(rows);
    const float4* h4 = reinterpret_cast<const float4*>(hs);
    r4[t] = h4[r0 * 64 + t];             // 4 rows * 64 float4
    __syncthreads();

    float aq[4] = {0,0,0,0}, ak[4] = {0,0,0,0}, av[4] = {0,0,0,0};
    for (int c = 0; c < NHID; ++c) {
        float wq = g_WqkvT[c * 768 + t];
        float wk = g_WqkvT[c * 768 + 256 + t];
        float wv = g_WqkvT[c * 768 + 512 + t];
        #pragma unroll
        for (int rr = 0; rr < 4; ++rr) {
            float hv = rows[rr * NHID + c];
            aq[rr] = fmaf(hv, wq, aq[rr]);
            ak[rr] = fmaf(hv, wk, ak[rr]);
            av[rr] = fmaf(hv, wv, av[rr]);
        }
    }
    int hh = t >> 5, d = t & 31;
    #pragma unroll
    for (int rr = 0; rr < 4; ++rr) {
        int r = r0 + rr; int b = r >> 6, l = r & 63;
        int idx = ((b * NH + hh) * NL + l) * ND + d;
        g_q[idx] = aq[rr] + bq[t];
        g_k[idx] = ak[rr] + bk[t];
        g_v[idx] = av[rr] + bv[t];
    }
}

// ---------------- K1b: kw = Wtk^T k, g_bk = btk . k ----------------
__global__ __launch_bounds__(256)
void k_kw(const float* __restrict__ Wtk, const float* __restrict__ btk)
{
    int w = threadIdx.x >> 5, e = threadIdx.x & 31;
    int idx = blockIdx.x * 8 + w;        // 512*8 = 4096 = B*H*L rows
    float kv = g_k[idx * ND + e];
    float acc = 0.f;
    #pragma unroll
    for (int d = 0; d < ND; ++d)
        acc = fmaf(Wtk[d * ND + e], __shfl_sync(0xffffffffu, kv, d), acc);
    g_kw[idx * ND + e] = acc;
    float r = btk[e] * kv;
    #pragma unroll
    for (int off = 16; off; off >>= 1) r += __shfl_xor_sync(0xffffffffu, r, off);
    if (e == 0) g_bk[idx] = r;
}

// ---------------- K2: sq, sv = structure @ Ws{q,v}^T + b ----------------
__global__ __launch_bounds__(256)
void k_sqsv(const float* __restrict__ structure, const float* __restrict__ bsq,
            const float* __restrict__ bsv)
{
    __shared__ __align__(16) float rows[16 * NHID];   // 16 structure rows
    int bx = blockIdx.x;                 // (b*64+i)*4 + jc  -> 2048 blocks
    int bi = bx >> 2, jc = bx & 3;
    int t = threadIdx.x;
    float4* r4 = reinterpret_cast<float4*>(rows);
    const float4* s4 = reinterpret_cast<const float4*>(structure);
    int base4 = (bi * 64 + jc * 16) * 64;
    #pragma unroll
    for (int u = 0; u < 4; ++u) r4[t + u * 256] = s4[base4 + t + u * 256];
    __syncthreads();

    int o2 = t & 63, rr = t >> 6;        // o2: 32 sq + 32 sv outputs, rr: row group
    float a0 = 0, a1 = 0, a2 = 0, a3 = 0;
    for (int c = 0; c < NHID; ++c) {
        float w = g_WsT[c * 64 + o2];
        a0 = fmaf(rows[(rr * 4 + 0) * NHID + c], w, a0);
        a1 = fmaf(rows[(rr * 4 + 1) * NHID + c], w, a1);
        a2 = fmaf(rows[(rr * 4 + 2) * NHID + c], w, a2);
        a3 = fmaf(rows[(rr * 4 + 3) * NHID + c], w, a3);
    }
    int e = o2 & 31;
    float bias = (o2 < 32) ? bsq[e] : bsv[e];
    float* dst = (o2 < 32) ? g_sq : g_sv;
    float acc[4] = {a0, a1, a2, a3};
    #pragma unroll
    for (int qq = 0; qq < 4; ++qq) {
        int j = jc * 16 + rr * 4 + qq;
        dst[(bi * NL + j) * ND + e] = acc[qq] + bias;
    }
}

// ---------------- K3: qw = Wtq^T q5, bq5 = btq . q5 ----------------
__global__ __launch_bounds__(256)
void k_qw(const float* __restrict__ Wtq, const float* __restrict__ btq)
{
    int p = blockIdx.x;                  // (b*64+i)*64 + j  -> 32768 blocks
    int b = p >> 12;
    int i = (p >> 6) & 63;
    int j = p & 63;
    int h = threadIdx.x >> 5, e = threadIdx.x & 31;
    float q5 = g_q[((b * NH + h) * NL + i) * ND + e]
             + g_q[((b * NH + h) * NL + j) * ND + e]
             + g_sq[p * ND + e];
    float acc = 0.f;
    #pragma unroll
    for (int d = 0; d < ND; ++d)
        acc = fmaf(Wtq[d * ND + e], __shfl_sync(0xffffffffu, q5, d), acc);
    g_qw[(p * NH + h) * ND + e] = acc;
    float r = btq[e] * q5;
    #pragma unroll
    for (int off = 16; off; off >>= 1) r += __shfl_xor_sync(0xffffffffu, r, off);
    if (e == 0) g_bq5[p * NH + h] = r;
}

// ---------------- cp.async helper ----------------
__device__ __forceinline__ void cp_async16(void* smem, const void* gmem)
{
    unsigned sa = (unsigned)__cvta_generic_to_shared(smem);
    asm volatile("cp.async.cg.shared.global [%0], [%1], 16;" :: "r"(sa), "l"(gmem));
}

// ---------------- MAIN: fused scores + online softmax + ctx partials ----
// grid = 512 blocks (b,i); 512 threads = (h,k).
__global__ __launch_bounds__(512, 1)
void k_main(const float* __restrict__ triple, const float* __restrict__ mask)
{
    const int bx = blockIdx.x;
    const int b  = bx >> 6, i = bx & 63;
    const int t  = threadIdx.x;
    const int h  = t >> 6, k = t & 63;

    __shared__ __align__(16) float4 trip_s[2][576];   // [k][d4] row-stride 9
    __shared__ __align__(16) float  q5_s[2][256];     // [h][d]
    __shared__ __align__(16) float  v5_s[2][256];
    __shared__ __align__(16) float  qw_s[2][256];
    __shared__ float bq5_s[2][8];
    __shared__ float mask_s[64];

    const float4* tg4 = reinterpret_cast<const float4*>(triple);
    const int h2 = t >> 5, d2 = t & 31;               // staging roles (t<256)

    float qi_r = 0.f, vi_r = 0.f;
    if (t < 256) {
        qi_r = g_q[((b * NH + h2) * NL + i) * ND + d2];
        vi_r = g_v[((b * NH + h2) * NL + i) * ND + d2];
    }
    if (t < 64) mask_s[t] = mask[b * NL + t];

    // per-thread constants: k row and kw row in registers
    float kvec[32], kw[32];
    {
        const float4* ka = reinterpret_cast<const float4*>(g_k  + ((b * NH + h) * NL + k) * ND);
        const float4* kb = reinterpret_cast<const float4*>(g_kw + ((b * NH + h) * NL + k) * ND);
        #pragma unroll
        for (int d4 = 0; d4 < 8; ++d4) {
            float4 x = ka[d4];
            kvec[4*d4+0] = x.x; kvec[4*d4+1] = x.y; kvec[4*d4+2] = x.z; kvec[4*d4+3] = x.w;
            float4 y = kb[d4];
            kw[4*d4+0] = y.x; kw[4*d4+1] = y.y; kw[4*d4+2] = y.z; kw[4*d4+3] = y.w;
        }
    }
    const float bkdot = g_bk[(b * NH + h) * NL + k];
    const float mik = mask[b * NL + i] * mask[b * NL + k];

    // stage j = 0 into buffer 0
    cp_async16(&trip_s[0][(t >> 3) * 9 + (t & 7)], &tg4[(bx * 64 + 0) * 512 + t]);
    asm volatile("cp.async.commit_group;");
    if (t < 256) {
        int p = bx * 64 + 0;
        q5_s[0][t] = qi_r + g_q[((b * NH + h2) * NL + 0) * ND + d2] + g_sq[p * ND + d2];
        v5_s[0][t] = vi_r + g_v[((b * NH + h2) * NL + 0) * ND + d2] + g_sv[p * ND + d2];
        qw_s[0][t] = g_qw[p * 256 + t];
    }
    if (t < 8) bq5_s[0][t] = g_bq5[(bx * 64 + 0) * NH + t];
    asm volatile("cp.async.wait_group 0;");
    __syncthreads();

    float C[32];
    #pragma unroll
    for (int d = 0; d < 32; ++d) C[d] = 0.f;
    float Z = 0.f;

    for (int j = 0; j < 64; ++j) {
        const int cur = j & 1, nxt = cur ^ 1;
        const int jn = (j < 63) ? j + 1 : 63;

        // prefetch j+1 (triple tile via cp.async; small arrays via registers)
        cp_async16(&trip_s[nxt][(t >> 3) * 9 + (t & 7)], &tg4[(bx * 64 + jn) * 512 + t]);
        asm volatile("cp.async.commit_group;");
        float q5n = 0.f, v5n = 0.f, qwn = 0.f, bn = 0.f;
        if (t < 256) {
            int p = bx * 64 + jn;
            q5n = qi_r + g_q[((b * NH + h2) * NL + jn) * ND + d2] + g_sq[p * ND + d2];
            v5n = vi_r + g_v[((b * NH + h2) * NL + jn) * ND + d2] + g_sv[p * ND + d2];
            qwn = g_qw[p * 256 + t];
        }
        if (t < 8) bn = g_bq5[(bx * 64 + jn) * NH + t];

        // score for current j:
        // s = q5.k + trip.(qw + kw) + bq5 + bk
        float s = bq5_s[cur][h] + bkdot;
        const float4* tb  = &trip_s[cur][k * 9];
        const float4* q54 = reinterpret_cast<const float4*>(&q5_s[cur][h * ND]);
        const float4* qw4 = reinterpret_cast<const float4*>(&qw_s[cur][h * ND]);
        #pragma unroll
        for (int d4 = 0; d4 < 8; ++d4) {
            float4 tp = tb[d4];
            float4 qa = q54[d4];
            float4 qq = qw4[d4];
            s = fmaf(kvec[4*d4+0], qa.x, s);  s = fmaf(tp.x, qq.x + kw[4*d4+0], s);
            s = fmaf(kvec[4*d4+1], qa.y, s);  s = fmaf(tp.y, qq.y + kw[4*d4+1], s);
            s = fmaf(kvec[4*d4+2], qa.z, s);  s = fmaf(tp.z, qq.z + kw[4*d4+2], s);
            s = fmaf(kvec[4*d4+3], qa.w, s);  s = fmaf(tp.w, qq.w + kw[4*d4+3], s);
        }
        s = fmaf(s, 0.17677669529663687f, mik * mask_s[j]);   // /sqrt(32) + mask3
        float w = __expf(s);
        Z += w;
        const float4* v54 = reinterpret_cast<const float4*>(&v5_s[cur][h * ND]);
        #pragma unroll
        for (int d4 = 0; d4 < 8; ++d4) {
            float4 vv = v54[d4];
            C[4*d4+0] = fmaf(w, vv.x, C[4*d4+0]);
            C[4*d4+1] = fmaf(w, vv.y, C[4*d4+1]);
            C[4*d4+2] = fmaf(w, vv.z, C[4*d4+2]);
            C[4*d4+3] = fmaf(w, vv.w, C[4*d4+3]);
        }

        // store staged smalls into nxt (safe: nxt last read at j-1, fenced by prev sync)
        if (t < 256) { q5_s[nxt][t] = q5n; v5_s[nxt][t] = v5n; qw_s[nxt][t] = qwn; }
        if (t < 8) bq5_s[nxt][t] = bn;
        asm volatile("cp.async.wait_group 0;");
        __syncthreads();
    }

    // write partials: Z[b,i,h,k], C[b,i,h,k,d]
    g_Zp[bx * 512 + t] = Z;
    float4* cp = reinterpret_cast<float4*>(g_Cp + (bx * 512 + t) * ND);
    #pragma unroll
    for (int d4 = 0; d4 < 8; ++d4)
        cp[d4] = make_float4(C[4*d4+0], C[4*d4+1], C[4*d4+2], C[4*d4+3]);
}

// ---------------- Reduce partials over i; write output [b][k][h*32+d] ----
__global__ __launch_bounds__(256)
void k_reduce(float* __restrict__ out)
{
    const int blk = blockIdx.x;          // b*64 + kk (512 blocks)
    const int b = blk >> 6, kk = blk & 63;
    const int t = threadIdx.x;           // h*32 + d
    const int h = t >> 5, d = t & 31;
    const int zb = (b * 64) * 512 + h * 64 + kk;
    float sz = 0.f, sc = 0.f;
    #pragma unroll 4
    for (int i = 0; i < 64; ++i) {
        sz += g_Zp[zb + i * 512];
        sc += g_Cp[(zb + i * 512) * ND + d];
    }
    out[blk * 256 + t] = sc / sz;
}

// ---------------- launch ----------------
extern "C" void kernel_launch(void* const* d_in, const int* in_sizes, int n_in,
                              void* d_out, int out_size)
{
    const float* hs        = (const float*)d_in[0];
    const float* mask      = (const float*)d_in[1];
    const float* structure = (const float*)d_in[2];
    const float* triple    = (const float*)d_in[3];
    const float* Wq  = (const float*)d_in[4];
    const float* bq  = (const float*)d_in[5];
    const float* Wk  = (const float*)d_in[6];
    const float* bk  = (const float*)d_in[7];
    const float* Wv  = (const float*)d_in[8];
    const float* bv  = (const float*)d_in[9];
    const float* Wsq = (const float*)d_in[10];
    const float* bsq = (const float*)d_in[11];
    const float* Wsv = (const float*)d_in[12];
    const float* bsv = (const float*)d_in[13];
    const float* Wtq = (const float*)d_in[14];
    const float* btq = (const float*)d_in[15];
    const float* Wtk = (const float*)d_in[16];
    const float* btk = (const float*)d_in[17];
    float* out = (float*)d_out;

    k_prep <<<256, 768>>>(Wq, Wk, Wv, Wsq, Wsv);
    k_qkv  <<<128, 256>>>(hs, bq, bk, bv);
    k_kw   <<<512, 256>>>(Wtk, btk);
    k_sqsv <<<2048, 256>>>(structure, bsq, bsv);
    k_qw   <<<32768, 256>>>(Wtq, btq);
    k_main <<<512, 512>>>(triple, mask);
    k_reduce<<<512, 256>>>(out);
}

// round 13
// speedup vs baseline: 1.1111x; 1.1111x over previous
#include <cuda_runtime.h>
#include <cuda_bf16.h>

#define NB   8
#define NL   64
#define NH   8
#define ND   32
#define NHID 256

// ---------------- static scratch (no runtime allocation) ----------------
__device__ __align__(16) float g_WqkvT[NHID * 3 * NHID];   // [c][m*256+o]
__device__ __align__(16) float g_WsT[NHID * 64];           // [c][o2] (sq|sv)
__device__ __align__(16) float g_q  [NB * NH * NL * ND];   // [b][h][l][d]
__device__ __align__(16) float g_k  [NB * NH * NL * ND];
__device__ __align__(16) float g_v  [NB * NH * NL * ND];
__device__ __align__(16) float g_kw [NB * NH * NL * ND];   // Wtk^T k
__device__ __align__(16) float g_qwl[NB * NH * NL * ND];   // Wtq^T q
__device__ float g_bk [NB * NH * NL];                      // btk . k
__device__ float g_bdq[NB * NH * NL];                      // btq . q
__device__ __align__(16) float g_sq [NB * NL * NL * ND];   // [b][i][j][d]
__device__ __align__(16) float g_sv [NB * NL * NL * ND];
__device__ __align__(16) float g_sqw[NB * NL * NL * ND];   // Wtq^T sq
__device__ float g_bsqd[NB * NL * NL];                     // btq . sq
__device__ float g_Zp[NB * NL * 2 * NH * NL];              // [pair][half][h*64+k]
__device__ __align__(16) float g_Cp[NB * NL * 2 * NH * NL * ND];

// ---------------- K0: transpose weights ----------------
__global__ void k_prep(const float* __restrict__ Wq, const float* __restrict__ Wk,
                       const float* __restrict__ Wv, const float* __restrict__ Wsq,
                       const float* __restrict__ Wsv)
{
    int c = blockIdx.x;                  // 0..255
    int t = threadIdx.x;                 // 0..767
    int m = t >> 8, o = t & 255;
    const float* W = (m == 0) ? Wq : (m == 1) ? Wk : Wv;
    g_WqkvT[c * 768 + t] = W[o * NHID + c];
    if (t < 64)
        g_WsT[c * 64 + t] = (t < 32) ? Wsq[t * NHID + c] : Wsv[(t - 32) * NHID + c];
}

// ---------------- K1: q,k,v projections (4 rows / block) ----------------
__global__ __launch_bounds__(256)
void k_qkv(const float* __restrict__ hs, const float* __restrict__ bq,
           const float* __restrict__ bk, const float* __restrict__ bv)
{
    __shared__ __align__(16) float rows[4 * NHID];
    int r0 = blockIdx.x * 4;             // 128 blocks * 4 = 512 rows (b*64+l)
    int t = threadIdx.x;                 // output channel o
    float4* r4 = reinterpret_cast<float4*>(rows);
    const float4* h4 = reinterpret_cast<const float4*>(hs);
    r4[t] = h4[r0 * 64 + t];
    __syncthreads();

    float aq[4] = {0,0,0,0}, ak[4] = {0,0,0,0}, av[4] = {0,0,0,0};
    #pragma unroll 2
    for (int c4 = 0; c4 < 64; ++c4) {
        float wq[4], wk[4], wv[4];
        #pragma unroll
        for (int u = 0; u < 4; ++u) {
            int c = c4 * 4 + u;
            wq[u] = g_WqkvT[c * 768 + t];
            wk[u] = g_WqkvT[c * 768 + 256 + t];
            wv[u] = g_WqkvT[c * 768 + 512 + t];
        }
        #pragma unroll
        for (int rr = 0; rr < 4; ++rr) {
            float4 hv = reinterpret_cast<const float4*>(rows)[rr * 64 + c4];
            aq[rr] = fmaf(hv.x, wq[0], aq[rr]); aq[rr] = fmaf(hv.y, wq[1], aq[rr]);
            aq[rr] = fmaf(hv.z, wq[2], aq[rr]); aq[rr] = fmaf(hv.w, wq[3], aq[rr]);
            ak[rr] = fmaf(hv.x, wk[0], ak[rr]); ak[rr] = fmaf(hv.y, wk[1], ak[rr]);
            ak[rr] = fmaf(hv.z, wk[2], ak[rr]); ak[rr] = fmaf(hv.w, wk[3], ak[rr]);
            av[rr] = fmaf(hv.x, wv[0], av[rr]); av[rr] = fmaf(hv.y, wv[1], av[rr]);
            av[rr] = fmaf(hv.z, wv[2], av[rr]); av[rr] = fmaf(hv.w, wv[3], av[rr]);
        }
    }
    int hh = t >> 5, d = t & 31;
    #pragma unroll
    for (int rr = 0; rr < 4; ++rr) {
        int r = r0 + rr; int b = r >> 6, l = r & 63;
        int idx = ((b * NH + hh) * NL + l) * ND + d;
        g_q[idx] = aq[rr] + bq[t];
        g_k[idx] = ak[rr] + bk[t];
        g_v[idx] = av[rr] + bv[t];
    }
}

// ---------------- K1b: per-(b,h,l) transforms: qwl, kw, bdq, bk ----------
__global__ __launch_bounds__(256)
void k_small(const float* __restrict__ Wtq, const float* __restrict__ btq,
             const float* __restrict__ Wtk, const float* __restrict__ btk)
{
    int w = threadIdx.x >> 5, e = threadIdx.x & 31;
    int idx = blockIdx.x * 8 + w;        // 512*8 = 4096 = B*H*L rows
    float qv = g_q[idx * ND + e];
    float kv = g_k[idx * ND + e];
    float aq = 0.f, ak = 0.f;
    #pragma unroll
    for (int d = 0; d < ND; ++d) {
        float qd = __shfl_sync(0xffffffffu, qv, d);
        float kd = __shfl_sync(0xffffffffu, kv, d);
        aq = fmaf(Wtq[d * ND + e], qd, aq);
        ak = fmaf(Wtk[d * ND + e], kd, ak);
    }
    g_qwl[idx * ND + e] = aq;
    g_kw [idx * ND + e] = ak;
    float rq = btq[e] * qv, rk = btk[e] * kv;
    #pragma unroll
    for (int off = 16; off; off >>= 1) {
        rq += __shfl_xor_sync(0xffffffffu, rq, off);
        rk += __shfl_xor_sync(0xffffffffu, rk, off);
    }
    if (e == 0) { g_bdq[idx] = rq; g_bk[idx] = rk; }
}

// ---------------- K2: sq, sv = structure @ Ws{q,v}^T + b (vectorized) ----
__global__ __launch_bounds__(256)
void k_sqsv(const float* __restrict__ structure, const float* __restrict__ bsq,
            const float* __restrict__ bsv)
{
    __shared__ __align__(16) float rows[16 * NHID];   // 16 structure rows
    int bx = blockIdx.x;                 // (b*64+i)*4 + jc  -> 2048 blocks
    int bi = bx >> 2, jc = bx & 3;
    int t = threadIdx.x;
    float4* r4 = reinterpret_cast<float4*>(rows);
    const float4* s4 = reinterpret_cast<const float4*>(structure);
    int base4 = (bi * 64 + jc * 16) * 64;
    #pragma unroll
    for (int u = 0; u < 4; ++u) r4[t + u * 256] = s4[base4 + t + u * 256];
    __syncthreads();

    int o2 = t & 63, rr = t >> 6;        // o2: 32 sq + 32 sv outputs
    float a0 = 0, a1 = 0, a2 = 0, a3 = 0;
    #pragma unroll 4
    for (int c4 = 0; c4 < 64; ++c4) {
        float w0 = g_WsT[(c4 * 4 + 0) * 64 + o2];
        float w1 = g_WsT[(c4 * 4 + 1) * 64 + o2];
        float w2 = g_WsT[(c4 * 4 + 2) * 64 + o2];
        float w3 = g_WsT[(c4 * 4 + 3) * 64 + o2];
        float4 v0 = r4[(rr * 4 + 0) * 64 + c4];
        float4 v1 = r4[(rr * 4 + 1) * 64 + c4];
        float4 v2 = r4[(rr * 4 + 2) * 64 + c4];
        float4 v3 = r4[(rr * 4 + 3) * 64 + c4];
        a0 = fmaf(v0.x, w0, a0); a0 = fmaf(v0.y, w1, a0); a0 = fmaf(v0.z, w2, a0); a0 = fmaf(v0.w, w3, a0);
        a1 = fmaf(v1.x, w0, a1); a1 = fmaf(v1.y, w1, a1); a1 = fmaf(v1.z, w2, a1); a1 = fmaf(v1.w, w3, a1);
        a2 = fmaf(v2.x, w0, a2); a2 = fmaf(v2.y, w1, a2); a2 = fmaf(v2.z, w2, a2); a2 = fmaf(v2.w, w3, a2);
        a3 = fmaf(v3.x, w0, a3); a3 = fmaf(v3.y, w1, a3); a3 = fmaf(v3.z, w2, a3); a3 = fmaf(v3.w, w3, a3);
    }
    int e = o2 & 31;
    float bias = (o2 < 32) ? bsq[e] : bsv[e];
    float* dst = (o2 < 32) ? g_sq : g_sv;
    float acc[4] = {a0, a1, a2, a3};
    #pragma unroll
    for (int qq = 0; qq < 4; ++qq) {
        int j = jc * 16 + rr * 4 + qq;
        dst[(bi * NL + j) * ND + e] = acc[qq] + bias;
    }
}

// ---------------- K3: sqw = Wtq^T sq, bsqd = btq . sq ----------------
__global__ __launch_bounds__(256)
void k_sqw(const float* __restrict__ Wtq, const float* __restrict__ btq)
{
    int w = threadIdx.x >> 5, e = threadIdx.x & 31;
    int row = blockIdx.x * 8 + w;        // 4096*8 = 32768 = B*L*L rows
    float sv = g_sq[row * ND + e];
    float acc = 0.f;
    #pragma unroll
    for (int d = 0; d < ND; ++d)
        acc = fmaf(Wtq[d * ND + e], __shfl_sync(0xffffffffu, sv, d), acc);
    g_sqw[row * ND + e] = acc;
    float r = btq[e] * sv;
    #pragma unroll
    for (int off = 16; off; off >>= 1) r += __shfl_xor_sync(0xffffffffu, r, off);
    if (e == 0) g_bsqd[row] = r;
}

// ---------------- cp.async helper ----------------
__device__ __forceinline__ void cp_async16(void* smem, const void* gmem)
{
    unsigned sa = (unsigned)__cvta_generic_to_shared(smem);
    asm volatile("cp.async.cg.shared.global [%0], [%1], 16;" :: "r"(sa), "l"(gmem));
}

// ---------------- MAIN: fused scores + online softmax + ctx partials ----
// grid = 1024 blocks: (b,i) x j-half; 512 threads = (h,k).
__global__ __launch_bounds__(512, 1)
void k_main(const float* __restrict__ triple, const float* __restrict__ mask)
{
    const int bx2  = blockIdx.x;
    const int pair = bx2 >> 1;           // b*64 + i
    const int half = bx2 & 1;
    const int b  = pair >> 6, i = pair & 63;
    const int j0 = half * 32;
    const int t  = threadIdx.x;
    const int h  = t >> 6, k = t & 63;

    __shared__ __align__(16) float4 trip_s[3][576];   // [k][d4] row-stride 9
    __shared__ __align__(16) float  q5_s[2][256];     // [h][d]
    __shared__ __align__(16) float  v5_s[2][256];
    __shared__ __align__(16) float  qw_s[2][256];
    __shared__ float bq5_s[2][8];
    __shared__ float mask_s[64];

    const float4* tg4 = reinterpret_cast<const float4*>(triple);
    const int h2 = t >> 5, d2 = t & 31;               // staging roles (t<256)

    float qi_r = 0.f, vi_r = 0.f, qwl_i_r = 0.f, bdq_i_r = 0.f;
    if (t < 256) {
        qi_r    = g_q  [((b * NH + h2) * NL + i) * ND + d2];
        vi_r    = g_v  [((b * NH + h2) * NL + i) * ND + d2];
        qwl_i_r = g_qwl[((b * NH + h2) * NL + i) * ND + d2];
    }
    if (t < 8) bdq_i_r = g_bdq[(b * NH + t) * NL + i];
    if (t < 64) mask_s[t] = mask[b * NL + t];

    // per-thread constants: k row and kw row in registers
    float kvec[32], kw[32];
    {
        const float4* ka = reinterpret_cast<const float4*>(g_k  + ((b * NH + h) * NL + k) * ND);
        const float4* kb = reinterpret_cast<const float4*>(g_kw + ((b * NH + h) * NL + k) * ND);
        #pragma unroll
        for (int d4 = 0; d4 < 8; ++d4) {
            float4 x = ka[d4];
            kvec[4*d4+0] = x.x; kvec[4*d4+1] = x.y; kvec[4*d4+2] = x.z; kvec[4*d4+3] = x.w;
            float4 y = kb[d4];
            kw[4*d4+0] = y.x; kw[4*d4+1] = y.y; kw[4*d4+2] = y.z; kw[4*d4+3] = y.w;
        }
    }
    const float bkdot = g_bk[(b * NH + h) * NL + k];
    const float mik = mask[b * NL + i] * mask[b * NL + k];

    // ---- prologue: stage triple rows j0, j0+1; smalls for j0 ----
    cp_async16(&trip_s[0][(t >> 3) * 9 + (t & 7)], &tg4[(pair * 64 + j0) * 512 + t]);
    asm volatile("cp.async.commit_group;");          // G0
    cp_async16(&trip_s[1][(t >> 3) * 9 + (t & 7)], &tg4[(pair * 64 + j0 + 1) * 512 + t]);
    asm volatile("cp.async.commit_group;");          // G1
    if (t < 256) {
        int p = pair * 64 + j0;
        q5_s[0][t] = qi_r + g_q[((b * NH + h2) * NL + j0) * ND + d2] + g_sq[p * ND + d2];
        v5_s[0][t] = vi_r + g_v[((b * NH + h2) * NL + j0) * ND + d2] + g_sv[p * ND + d2];
        qw_s[0][t] = qwl_i_r + g_qwl[((b * NH + h2) * NL + j0) * ND + d2] + g_sqw[p * ND + d2];
    }
    if (t < 8)
        bq5_s[0][t] = bdq_i_r + g_bdq[(b * NH + t) * NL + j0] + g_bsqd[pair * 64 + j0];
    asm volatile("cp.async.wait_group 1;");          // G0 done
    __syncthreads();

    float C[32];
    #pragma unroll
    for (int d = 0; d < 32; ++d) C[d] = 0.f;
    float Z = 0.f;

    for (int jj = 0; jj < 32; ++jj) {
        const int j = j0 + jj;
        const int cur = jj & 1, nxt = cur ^ 1;

        // prefetch triple row j+2 (distance 2, 3 buffers)
        if (jj < 30)
            cp_async16(&trip_s[(jj + 2) % 3][(t >> 3) * 9 + (t & 7)],
                       &tg4[(pair * 64 + j + 2) * 512 + t]);
        asm volatile("cp.async.commit_group;");

        // load smalls for j+1 into regs
        const int jn = (jj < 31) ? j + 1 : j;
        float q5n = 0.f, v5n = 0.f, qwn = 0.f, bn = 0.f;
        if (t < 256) {
            int p = pair * 64 + jn;
            q5n = qi_r + g_q[((b * NH + h2) * NL + jn) * ND + d2] + g_sq[p * ND + d2];
            v5n = vi_r + g_v[((b * NH + h2) * NL + jn) * ND + d2] + g_sv[p * ND + d2];
            qwn = qwl_i_r + g_qwl[((b * NH + h2) * NL + jn) * ND + d2] + g_sqw[p * ND + d2];
        }
        if (t < 8)
            bn = bdq_i_r + g_bdq[(b * NH + t) * NL + jn] + g_bsqd[pair * 64 + jn];

        // score: s = q5.k + trip.(qw + kw) + bq5 + bk
        float s = bq5_s[cur][h] + bkdot;
        const float4* tb  = &trip_s[jj % 3][k * 9];
        const float4* q54 = reinterpret_cast<const float4*>(&q5_s[cur][h * ND]);
        const float4* qw4 = reinterpret_cast<const float4*>(&qw_s[cur][h * ND]);
        #pragma unroll
        for (int d4 = 0; d4 < 8; ++d4) {
            float4 tp = tb[d4];
            float4 qa = q54[d4];
            float4 qq = qw4[d4];
            s = fmaf(kvec[4*d4+0], qa.x, s);  s = fmaf(tp.x, qq.x + kw[4*d4+0], s);
            s = fmaf(kvec[4*d4+1], qa.y, s);  s = fmaf(tp.y, qq.y + kw[4*d4+1], s);
            s = fmaf(kvec[4*d4+2], qa.z, s);  s = fmaf(tp.z, qq.z + kw[4*d4+2], s);
            s = fmaf(kvec[4*d4+3], qa.w, s);  s = fmaf(tp.w, qq.w + kw[4*d4+3], s);
        }
        s = fmaf(s, 0.17677669529663687f, mik * mask_s[j]);   // /sqrt(32) + mask3
        float w = __expf(s);
        Z += w;
        const float4* v54 = reinterpret_cast<const float4*>(&v5_s[cur][h * ND]);
        #pragma unroll
        for (int d4 = 0; d4 < 8; ++d4) {
            float4 vv = v54[d4];
            C[4*d4+0] = fmaf(w, vv.x, C[4*d4+0]);
            C[4*d4+1] = fmaf(w, vv.y, C[4*d4+1]);
            C[4*d4+2] = fmaf(w, vv.z, C[4*d4+2]);
            C[4*d4+3] = fmaf(w, vv.w, C[4*d4+3]);
        }

        // stash smalls for j+1
        if (t < 256) { q5_s[nxt][t] = q5n; v5_s[nxt][t] = v5n; qw_s[nxt][t] = qwn; }
        if (t < 8) bq5_s[nxt][t] = bn;
        asm volatile("cp.async.wait_group 1;");
        __syncthreads();
    }

    // write partials
    g_Zp[bx2 * 512 + t] = Z;
    float4* cp = reinterpret_cast<float4*>(g_Cp + (bx2 * 512 + t) * ND);
    #pragma unroll
    for (int d4 = 0; d4 < 8; ++d4)
        cp[d4] = make_float4(C[4*d4+0], C[4*d4+1], C[4*d4+2], C[4*d4+3]);
}

// ---------------- Reduce partials over (i, half); out [b][k][h*32+d] ----
__global__ __launch_bounds__(256)
void k_reduce(float* __restrict__ out)
{
    const int blk = blockIdx.x;          // b*64 + kk (512 blocks)
    const int b = blk >> 6, kk = blk & 63;
    const int t = threadIdx.x;           // h*32 + d
    const int h = t >> 5, d = t & 31;
    float sz = 0.f, sc = 0.f;
    #pragma unroll 4
    for (int u = 0; u < 128; ++u) {      // u = i*2 + half
        int bi = (b * 64) * 2 + u;       // bx2 of partial
        int zi = bi * 512 + h * 64 + kk;
        sz += g_Zp[zi];
        sc += g_Cp[zi * ND + d];
    }
    out[blk * 256 + t] = sc / sz;
}

// ---------------- launch ----------------
extern "C" void kernel_launch(void* const* d_in, const int* in_sizes, int n_in,
                              void* d_out, int out_size)
{
    const float* hs        = (const float*)d_in[0];
    const float* mask      = (const float*)d_in[1];
    const float* structure = (const float*)d_in[2];
    const float* triple    = (const float*)d_in[3];
    const float* Wq  = (const float*)d_in[4];
    const float* bq  = (const float*)d_in[5];
    const float* Wk  = (const float*)d_in[6];
    const float* bk  = (const float*)d_in[7];
    const float* Wv  = (const float*)d_in[8];
    const float* bv  = (const float*)d_in[9];
    const float* Wsq = (const float*)d_in[10];
    const float* bsq = (const float*)d_in[11];
    const float* Wsv = (const float*)d_in[12];
    const float* bsv = (const float*)d_in[13];
    const float* Wtq = (const float*)d_in[14];
    const float* btq = (const float*)d_in[15];
    const float* Wtk = (const float*)d_in[16];
    const float* btk = (const float*)d_in[17];
    float* out = (float*)d_out;

    k_prep <<<256, 768>>>(Wq, Wk, Wv, Wsq, Wsv);
    k_qkv  <<<128, 256>>>(hs, bq, bk, bv);
    k_small<<<512, 256>>>(Wtq, btq, Wtk, btk);
    k_sqsv <<<2048, 256>>>(structure, bsq, bsv);
    k_sqw  <<<4096, 256>>>(Wtq, btq);
    k_main <<<1024, 512>>>(triple, mask);
    k_reduce<<<512, 256>>>(out);
}